// round 11
// baseline (speedup 1.0000x reference)
#include <cuda_runtime.h>

#define B 8
#define L 2048
#define H 8
#define D 64
#define S 40
#define U 40
#define NBH (B*H)
#define SPLIT 8
#define CHUNK (L/SPLIT)   // 256 (K5 key chunk)
#define KCH 256           // K1: key rows per chunk
#define NCH 8             // K1: key chunks
#define LCH 256           // K1: queries per block
#define NEG_INF (-3.4e38f)

typedef unsigned long long ull;
typedef unsigned int uint;

// ---------------- f32x2 helpers ----------------
__device__ __forceinline__ ull pk2(float a, float b) {
    ull r; asm("mov.b64 %0,{%1,%2};" : "=l"(r) : "f"(a), "f"(b)); return r;
}
__device__ __forceinline__ void upk2(ull v, float& a, float& b) {
    asm("mov.b64 {%0,%1},%2;" : "=f"(a), "=f"(b) : "l"(v));
}
__device__ __forceinline__ ull fma2_(ull a, ull b, ull c) {
    ull d; asm("fma.rn.f32x2 %0,%1,%2,%3;" : "=l"(d) : "l"(a), "l"(b), "l"(c)); return d;
}
__device__ __forceinline__ ull add2_(ull a, ull b) {
    ull d; asm("add.rn.f32x2 %0,%1,%2;" : "=l"(d) : "l"(a), "l"(b)); return d;
}

// ---------------- scratch (device globals; no allocation) ----------------
__device__ uint     g_bidxw[L*S/4];       // per-l sample rows as bytes, sorted by chunk
__device__ uint     g_bcntw[L*2];         // per-l 8 chunk counts as bytes
__device__ float    g_M[NBH*L];           // sparsity metric
__device__ int      g_Mtop[NBH*U];        // top-U query indices per bh
__device__ float    g_Vpart[NBH*SPLIT*D]; // partial V sums
__device__ float2   g_pO2[NBH*SPLIT*U*D/2]; // split attention partial outputs
__device__ float    g_pm[NBH*SPLIT*U];    // split local max
__device__ float    g_pl[NBH*SPLIT*U];    // split local sum-exp

// ---------------- K0: warp-per-query ballot bucketing ----------------
__global__ void __launch_bounds__(256) k0_bucket(const int* __restrict__ idxs) {
    int w = threadIdx.x >> 5, lane = threadIdx.x & 31;
    int l = blockIdx.x * 8 + w;                     // 256 blocks x 8 warps = 2048
    const int* p = idxs + l * S;
    int v0 = p[lane];
    int c0v = v0 >> 8;
    int v1 = 0, c1v = -1;
    if (lane < 8) { v1 = p[32 + lane]; c1v = v1 >> 8; }
    unsigned m0[NCH], m1[NCH];
    int cnt[NCH];
    #pragma unroll
    for (int cc = 0; cc < NCH; cc++) {
        m0[cc] = __ballot_sync(0xffffffffu, c0v == cc);
        m1[cc] = __ballot_sync(0xffffffffu, c1v == cc);
        cnt[cc] = __popc(m0[cc]) + __popc(m1[cc]);
    }
    int basep[NCH];
    int run = 0;
    #pragma unroll
    for (int cc = 0; cc < NCH; cc++) { basep[cc] = run; run += cnt[cc]; }
    unsigned lt = (1u << lane) - 1u;
    unsigned char* bp = (unsigned char*)g_bidxw + l*S;
    int pos0 = basep[c0v] + __popc(m0[c0v] & lt);
    bp[pos0] = (unsigned char)(v0 & 255);
    if (lane < 8) {
        int pos1 = basep[c1v] + __popc(m0[c1v]) + __popc(m1[c1v] & lt);
        bp[pos1] = (unsigned char)(v1 & 255);
    }
    if (lane == 0) {
        g_bcntw[l*2    ] = (uint)cnt[0] | ((uint)cnt[1] << 8) | ((uint)cnt[2] << 16) | ((uint)cnt[3] << 24);
        g_bcntw[l*2 + 1] = (uint)cnt[4] | ((uint)cnt[5] << 8) | ((uint)cnt[6] << 16) | ((uint)cnt[7] << 24);
    }
}

// ---------------- K1: lane-pair-per-query (split dot), smem K chunks ----------------
// block = (bh, 256-query panel), 512 threads. thread = (query, half-of-D).
#define SMEM1_BYTES (KCH*D*4 + LCH*S)   // 65536 + 10240 = 75776

__global__ void __launch_bounds__(512, 2) k1_pair(const float* __restrict__ Qg,
                                                  const float* __restrict__ Kg) {
    int bh = blockIdx.x >> 3, lch = blockIdx.x & 7;
    int b = bh >> 3, h = bh & 7;
    int l0 = lch * LCH;
    int t = threadIdx.x, lane = t & 31;
    int sub = t & 1;            // which half of D
    int q   = t >> 1;           // query 0..255
    int qi  = lane >> 1;        // query-in-warp 0..15
    extern __shared__ float sm[];
    float4* Ks4 = (float4*)sm;                           // 256 rows x 16 float4
    unsigned char* sByte = (unsigned char*)(sm + KCH*D); // 256 x 40 bytes

    // per-thread column order: 8 float4 cols in own half, rotated so each
    // 8-lane phase covers 8 distinct bank groups for ANY row set
    int offs[8];
    #pragma unroll
    for (int j = 0; j < 8; j++) offs[j] = sub*8 + ((j + qi + sub*4) & 7);

    // ---- stage Q panel into Ks4 (coalesced), idx bytes into sByte ----
    for (int e = t; e < LCH*16; e += 512) {
        int i = e >> 4, c4 = e & 15;
        Ks4[e] = __ldg((const float4*)(Qg + ((size_t)(b*L + l0 + i)*H + h)*D) + c4);
    }
    uint* sb32 = (uint*)sByte;
    for (int e = t; e < LCH*(S/4); e += 512)
        sb32[e] = g_bidxw[l0*(S/4) + e];
    __syncthreads();

    // own half-row of Q -> 16 regs (pre-rotated to match offs[])
    ull q0[8], q1[8];
    #pragma unroll
    for (int j = 0; j < 8; j++) {
        float4 v = Ks4[q*16 + offs[j]];
        q0[j] = pk2(v.x, v.y);
        q1[j] = pk2(v.z, v.w);
    }
    uint cw0 = g_bcntw[(l0 + q)*2];
    uint cw1 = g_bcntw[(l0 + q)*2 + 1];
    __syncthreads();

    unsigned pmask = 3u << (lane & ~1);   // the lane pair (always convergent)
    ull z = pk2(0.f, 0.f);
    float lmax = NEG_INF, lsum = 0.f;
    int p0 = q * S;

    for (int c = 0; c < NCH; c++) {
        const float* Kbase = Kg + (size_t)(b*L + c*KCH)*(H*D) + h*D;
        for (int e = t; e < KCH*16; e += 512) {
            int kk = e >> 4, c4 = e & 15;
            Ks4[e] = __ldg((const float4*)(Kbase + (size_t)kk*(H*D)) + c4);
        }
        __syncthreads();

        int cnt = (c < 4) ? (int)((cw0 >> (c*8)) & 255u)
                          : (int)((cw1 >> ((c-4)*8)) & 255u);
        if (cnt) {
            int row = sByte[p0];
            for (int j = 0; j < cnt; j++) {
                int jn = (j + 1 < cnt) ? j + 1 : j;
                int rown = sByte[p0 + jn];             // prefetch next index
                const float4* kp = Ks4 + row*16;
                ull a0 = z, a1 = z;
                #pragma unroll
                for (int jj = 0; jj < 8; jj++) {
                    float4 kv = kp[offs[jj]];
                    a0 = fma2_(q0[jj], pk2(kv.x, kv.y), a0);
                    a1 = fma2_(q1[jj], pk2(kv.z, kv.w), a1);
                }
                a0 = add2_(a0, a1);
                float lo, hi; upk2(a0, lo, hi);
                float pdot = lo + hi;
                pdot += __shfl_xor_sync(pmask, pdot, 1);  // combine the two halves
                lmax = fmaxf(lmax, pdot);
                lsum += pdot;
                row = rown;
            }
        }
        p0 += cnt;
        __syncthreads();
    }

    if (sub == 0)
        g_M[bh*L + l0 + q] = lmax - lsum * (1.0f / S);
}

// ---------------- K2: two-level top-U (warp-local lists, then merge) ----------------
__global__ void __launch_bounds__(256) k2_topk() {
    __shared__ float sv[L];
    __shared__ float wvs[8*U];
    __shared__ int   wis[8*U];
    int bh = blockIdx.x, tid = threadIdx.x;
    int lane = tid & 31, w = tid >> 5;
    for (int i = tid; i < L; i += 256) sv[i] = g_M[bh*L + i];
    __syncthreads();

    int base = w*256 + lane;
    float v[8];
    #pragma unroll
    for (int t = 0; t < 8; t++) v[t] = sv[base + t*32];
    for (int it = 0; it < U; it++) {
        float bv = v[0]; int bt = 0;
        #pragma unroll
        for (int t = 1; t < 8; t++)
            if (v[t] > bv) { bv = v[t]; bt = t; }
        int bi = base + bt*32;
        #pragma unroll
        for (int o = 16; o; o >>= 1) {
            float ov = __shfl_xor_sync(0xffffffffu, bv, o);
            int   oi = __shfl_xor_sync(0xffffffffu, bi, o);
            if (ov > bv || (ov == bv && oi < bi)) { bv = ov; bi = oi; }
        }
        int rel = bi - w*256;
        if ((rel & 31) == lane) v[rel >> 5] = NEG_INF;
        if (lane == 0) { wvs[w*U + it] = bv; wis[w*U + it] = bi; }
    }
    __syncthreads();

    if (w == 0) {
        float cv[10]; int ci[10];
        #pragma unroll
        for (int r = 0; r < 10; r++) { cv[r] = wvs[lane + 32*r]; ci[r] = wis[lane + 32*r]; }
        for (int it = 0; it < U; it++) {
            float bv = cv[0]; int bi = ci[0];
            #pragma unroll
            for (int r = 1; r < 10; r++)
                if (cv[r] > bv || (cv[r] == bv && ci[r] < bi)) { bv = cv[r]; bi = ci[r]; }
            #pragma unroll
            for (int o = 16; o; o >>= 1) {
                float ov = __shfl_xor_sync(0xffffffffu, bv, o);
                int   oi = __shfl_xor_sync(0xffffffffu, bi, o);
                if (ov > bv || (ov == bv && oi < bi)) { bv = ov; bi = oi; }
            }
            if (lane == 0) g_Mtop[bh*U + it] = bi;
            #pragma unroll
            for (int r = 0; r < 10; r++)
                if (ci[r] == bi) cv[r] = NEG_INF;
        }
    }
}

// ---------------- K3: partial V sums over L-chunks ----------------
__global__ void __launch_bounds__(256) k3_vsum(const float* __restrict__ Vg) {
    int bh = blockIdx.x >> 3, sp = blockIdx.x & 7;
    int b = bh >> 3, h = bh & 7;
    int d  = threadIdx.x & 63;
    int lg = threadIdx.x >> 6;
    const float* base = Vg + (size_t)b*L*(H*D) + h*D + d;
    int l0 = sp*CHUNK + lg;
    float a0 = 0.f, a1 = 0.f;
    #pragma unroll 8
    for (int i = 0; i < CHUNK/8; i++) {
        a0 += base[(size_t)(l0 + i*8    ) * (H*D)];
        a1 += base[(size_t)(l0 + i*8 + 4) * (H*D)];
    }
    __shared__ float red[4][64];
    red[lg][d] = a0 + a1;
    __syncthreads();
    if (threadIdx.x < 64)
        g_Vpart[(bh*SPLIT + sp)*D + threadIdx.x] =
            red[0][threadIdx.x] + red[1][threadIdx.x] + red[2][threadIdx.x] + red[3][threadIdx.x];
}

// ---------------- K4: broadcast V-mean into full output ----------------
__global__ void __launch_bounds__(256) k4_fill(float* __restrict__ out) {
    int b  = blockIdx.x >> 6;
    int r0 = (blockIdx.x & 63) * 32;
    __shared__ __align__(16) float vec[512];
    int tid = threadIdx.x;
    for (int j = tid; j < 512; j += 256) {
        int h = j >> 6, d = j & 63;
        float s = 0.f;
        #pragma unroll
        for (int sp = 0; sp < SPLIT; sp++)
            s += g_Vpart[((b*H + h)*SPLIT + sp)*D + d];
        vec[j] = s * (1.0f / L);
    }
    __syncthreads();
    float4* o4 = (float4*)(out + (size_t)(b*L + r0) * (H*D));
    const float4* v4 = (const float4*)vec;
    for (int e = tid; e < 32*128; e += 256) {
        int r = e >> 7, c = e & 127;
        o4[r*128 + c] = v4[c];
    }
}

// ---------------- K5: split-K sparse attention, f32x2, Qs aliased into Sc ----------------
#define SCW 264
#define SM5_KS 0
#define SM5_SC 16384
#define SMEM5_BYTES ((16384 + U*SCW) * 4)   // 107776

__global__ void __launch_bounds__(256, 2) k5_attn(const float* __restrict__ Qg,
                                                  const float* __restrict__ Kg,
                                                  const float* __restrict__ Vg) {
    int bh = blockIdx.x >> 3, sp = blockIdx.x & 7;
    int b = bh >> 3, h = bh & 7;
    int tid = threadIdx.x;
    extern __shared__ float sm[];
    float2* Ks2 = (float2*)(sm + SM5_KS);
    float*  Sc  = sm + SM5_SC;
    float*  Qs  = sm + SM5_SC;             // aliased: Qs dead after phase 1
    float2* Qs2 = (float2*)Qs;
    __shared__ int topq[U];

    if (tid < U) topq[tid] = g_Mtop[bh*U + tid];
    __syncthreads();

    for (int e = tid; e < U*D; e += 256) {
        int i = e >> 6, d = e & 63;
        Qs[e] = Qg[((size_t)(b*L + topq[i])*H + h)*D + d];
    }
    const float* Kbase = Kg + (size_t)(b*L + sp*CHUNK)*(H*D) + h*D;
    for (int e = tid; e < CHUNK*D/2; e += 256) {
        int kk = e >> 5, c2 = e & 31;
        Ks2[kk*32 + (c2 ^ (kk >> 3))] = *(const float2*)(Kbase + (size_t)kk*(H*D) + c2*2);
    }
    __syncthreads();

    int qg = tid >> 5, kg = tid & 31;
    ull z2 = pk2(0.f, 0.f);
    ull acc2[5][8];
    #pragma unroll
    for (int i = 0; i < 5; i++)
        #pragma unroll
        for (int j = 0; j < 8; j++) acc2[i][j] = z2;

    #pragma unroll 2
    for (int dd = 0; dd < 32; dd++) {
        ull qv[5], kv[8];
        #pragma unroll
        for (int i = 0; i < 5; i++) { float2 tq = Qs2[(qg*5 + i)*32 + dd]; qv[i] = pk2(tq.x, tq.y); }
        #pragma unroll
        for (int j = 0; j < 8; j++) { float2 tk = Ks2[(kg*8 + j)*32 + (dd ^ kg)]; kv[j] = pk2(tk.x, tk.y); }
        #pragma unroll
        for (int i = 0; i < 5; i++)
            #pragma unroll
            for (int j = 0; j < 8; j++) acc2[i][j] = fma2_(qv[i], kv[j], acc2[i][j]);
    }
    __syncthreads();   // ALL Qs/Ks reads done before Sc (aliased) writes & V load

    #pragma unroll
    for (int i = 0; i < 5; i++) {
        int q = qg*5 + i;
        float s[8];
        #pragma unroll
        for (int j = 0; j < 8; j++) { float lo, hi; upk2(acc2[i][j], lo, hi); s[j] = (lo + hi) * 0.125f; }
        float4* dst = (float4*)(Sc + q*SCW + kg*8);
        dst[0] = make_float4(s[0], s[1], s[2], s[3]);
        dst[1] = make_float4(s[4], s[5], s[6], s[7]);
    }
    const float* Vbase = Vg + (size_t)(b*L + sp*CHUNK)*(H*D) + h*D;
    for (int e = tid; e < CHUNK*D/2; e += 256) {
        int kk = e >> 5, c2 = e & 31;
        Ks2[kk*32 + (c2 ^ (kk >> 3))] = *(const float2*)(Vbase + (size_t)kk*(H*D) + c2*2);
    }
    __syncthreads();

    int lane = tid & 31;
    #pragma unroll
    for (int i = 0; i < 5; i++) {
        int q = qg*5 + i;
        float vals[8];
        float mv = NEG_INF;
        #pragma unroll
        for (int t = 0; t < 8; t++) {
            vals[t] = Sc[q*SCW + lane + t*32];
            mv = fmaxf(mv, vals[t]);
        }
        #pragma unroll
        for (int o = 16; o; o >>= 1) mv = fmaxf(mv, __shfl_xor_sync(0xffffffffu, mv, o));
        float ssum = 0.f;
        #pragma unroll
        for (int t = 0; t < 8; t++) {
            float ev = __expf(vals[t] - mv);
            Sc[q*SCW + lane + t*32] = ev;
            ssum += ev;
        }
        #pragma unroll
        for (int o = 16; o; o >>= 1) ssum += __shfl_xor_sync(0xffffffffu, ssum, o);
        if (lane == 0) {
            g_pm[(bh*SPLIT + sp)*U + q] = mv;
            g_pl[(bh*SPLIT + sp)*U + q] = ssum;
        }
    }
    __syncthreads();

    int kr  = tid >> 6;
    int r   = tid & 63;
    int qg2 = r >> 3, dg = r & 7;
    ull facc[5][4];
    #pragma unroll
    for (int i = 0; i < 5; i++)
        #pragma unroll
        for (int j = 0; j < 4; j++) facc[i][j] = z2;

    #pragma unroll 2
    for (int kl = 0; kl < 64; kl++) {
        int kk = kr*64 + kl;
        ull pv2[5], vv[4];
        #pragma unroll
        for (int i = 0; i < 5; i++) {
            float p = Sc[(qg2*5 + i)*SCW + kk];
            pv2[i] = pk2(p, p);
        }
        int sw = kk >> 3;
        #pragma unroll
        for (int j = 0; j < 4; j++) {
            float2 tv = Ks2[kk*32 + ((dg*4 + j) ^ sw)];
            vv[j] = pk2(tv.x, tv.y);
        }
        #pragma unroll
        for (int i = 0; i < 5; i++)
            #pragma unroll
            for (int j = 0; j < 4; j++) facc[i][j] = fma2_(pv2[i], vv[j], facc[i][j]);
    }
    __syncthreads();
    float2* Scr = (float2*)Sc;
    #pragma unroll
    for (int i = 0; i < 5; i++) {
        int q = qg2*5 + i;
        #pragma unroll
        for (int j = 0; j < 4; j++) {
            float lo, hi; upk2(facc[i][j], lo, hi);
            Scr[kr*1280 + q*32 + dg*4 + j] = make_float2(lo, hi);
        }
    }
    __syncthreads();
    float2* pO2 = g_pO2 + (size_t)(bh*SPLIT + sp)*U*D/2;
    for (int e = tid; e < U*D/2; e += 256) {
        float2 a = Scr[e], b2 = Scr[1280 + e], c = Scr[2560 + e], d2 = Scr[3840 + e];
        pO2[e] = make_float2(a.x + b2.x + c.x + d2.x, a.y + b2.y + c.y + d2.y);
    }
}

// ---------------- K6: combine splits + scatter to output ----------------
__global__ void __launch_bounds__(256) k6_combine(float* __restrict__ out) {
    int bh = blockIdx.x;
    int b = bh >> 3, h = bh & 7;
    __shared__ float w[U*SPLIT];
    __shared__ int topq[U];
    int tid = threadIdx.x;
    const float* gpO = (const float*)g_pO2;
    if (tid < U) {
        topq[tid] = g_Mtop[bh*U + tid];
        float pm_[SPLIT], pl_[SPLIT];
        float m = NEG_INF;
        #pragma unroll
        for (int sp = 0; sp < SPLIT; sp++) {
            pm_[sp] = g_pm[(bh*SPLIT + sp)*U + tid];
            pl_[sp] = g_pl[(bh*SPLIT + sp)*U + tid];
            m = fmaxf(m, pm_[sp]);
        }
        float denom = 0.f, e_[SPLIT];
        #pragma unroll
        for (int sp = 0; sp < SPLIT; sp++) {
            e_[sp] = __expf(pm_[sp] - m);
            denom += pl_[sp] * e_[sp];
        }
        float inv = 1.0f / denom;
        #pragma unroll
        for (int sp = 0; sp < SPLIT; sp++) w[tid*SPLIT + sp] = e_[sp] * inv;
    }
    __syncthreads();
    for (int e = tid; e < U*D; e += 256) {
        int q = e >> 6, d = e & 63;
        float s = 0.f;
        #pragma unroll
        for (int sp = 0; sp < SPLIT; sp++)
            s += gpO[((size_t)(bh*SPLIT + sp)*U + q)*D + d] * w[q*SPLIT + sp];
        out[((size_t)(b*L + topq[q])*H + h)*D + d] = s;
    }
}

// ---------------- launch ----------------
extern "C" void kernel_launch(void* const* d_in, const int* in_sizes, int n_in,
                              void* d_out, int out_size) {
    const float* Q   = (const float*)d_in[0];
    const float* K   = (const float*)d_in[1];
    const float* V   = (const float*)d_in[2];
    const int*  idxs = (const int*)d_in[3];
    float* out = (float*)d_out;

    cudaFuncSetAttribute(k1_pair, cudaFuncAttributeMaxDynamicSharedMemorySize, SMEM1_BYTES);
    cudaFuncSetAttribute(k5_attn, cudaFuncAttributeMaxDynamicSharedMemorySize, SMEM5_BYTES);

    // k1 stays 4th launch for the ncu capture slot
    k0_bucket <<<L/8,       256>>>(idxs);
    k3_vsum   <<<NBH*SPLIT, 256>>>(V);
    k4_fill   <<<B*64,      256>>>(out);
    k1_pair   <<<NBH*8,     512, SMEM1_BYTES>>>(Q, K);
    k2_topk   <<<NBH,       256>>>();
    k5_attn   <<<NBH*SPLIT, 256, SMEM5_BYTES>>>(Q, K, V);
    k6_combine<<<NBH,       256>>>(out);
}

// round 12
// speedup vs baseline: 1.0196x; 1.0196x over previous
#include <cuda_runtime.h>

#define B 8
#define L 2048
#define H 8
#define D 64
#define S 40
#define U 40
#define NBH (B*H)
#define SPLIT 8
#define CHUNK (L/SPLIT)   // 256 (K5 key chunk)
#define KCH4 512          // K1: key rows per chunk
#define NCH4 4            // K1: key chunks
#define LCH 256           // K1: queries per block
#define NEG_INF (-3.4e38f)

typedef unsigned long long ull;
typedef unsigned int uint;
typedef unsigned short ushort;

// ---------------- f32x2 helpers ----------------
__device__ __forceinline__ ull pk2(float a, float b) {
    ull r; asm("mov.b64 %0,{%1,%2};" : "=l"(r) : "f"(a), "f"(b)); return r;
}
__device__ __forceinline__ void upk2(ull v, float& a, float& b) {
    asm("mov.b64 {%0,%1},%2;" : "=f"(a), "=f"(b) : "l"(v));
}
__device__ __forceinline__ ull fma2_(ull a, ull b, ull c) {
    ull d; asm("fma.rn.f32x2 %0,%1,%2,%3;" : "=l"(d) : "l"(a), "l"(b), "l"(c)); return d;
}
__device__ __forceinline__ ull add2_(ull a, ull b) {
    ull d; asm("add.rn.f32x2 %0,%1,%2;" : "=l"(d) : "l"(a), "l"(b)); return d;
}

// ---------------- scratch (device globals; no allocation) ----------------
__device__ uint     g_bidxw[L*S/2];       // per-l sample rows as ushort, sorted by chunk
__device__ uint     g_bcnt4[L];           // per-l 4 chunk counts as bytes
__device__ float    g_M[NBH*L];           // sparsity metric
__device__ int      g_Mtop[NBH*U];        // top-U query indices per bh
__device__ float    g_Vpart[NBH*SPLIT*D]; // partial V sums
__device__ float2   g_pO2[NBH*SPLIT*U*D/2]; // split attention partial outputs
__device__ float    g_pm[NBH*SPLIT*U];    // split local max
__device__ float    g_pl[NBH*SPLIT*U];    // split local sum-exp

// ---------------- K0: warp-per-query ballot bucketing (4 buckets, ushort rows) ----------------
__global__ void __launch_bounds__(256) k0_bucket(const int* __restrict__ idxs) {
    int w = threadIdx.x >> 5, lane = threadIdx.x & 31;
    int l = blockIdx.x * 8 + w;                     // 256 blocks x 8 warps = 2048
    const int* p = idxs + l * S;
    int v0 = p[lane];
    int c0v = v0 >> 9;
    int v1 = 0, c1v = -1;
    if (lane < 8) { v1 = p[32 + lane]; c1v = v1 >> 9; }
    unsigned m0[NCH4], m1[NCH4];
    int cnt[NCH4];
    #pragma unroll
    for (int cc = 0; cc < NCH4; cc++) {
        m0[cc] = __ballot_sync(0xffffffffu, c0v == cc);
        m1[cc] = __ballot_sync(0xffffffffu, c1v == cc);
        cnt[cc] = __popc(m0[cc]) + __popc(m1[cc]);
    }
    int basep[NCH4];
    int run = 0;
    #pragma unroll
    for (int cc = 0; cc < NCH4; cc++) { basep[cc] = run; run += cnt[cc]; }
    unsigned lt = (1u << lane) - 1u;
    ushort* bp = (ushort*)g_bidxw + l*S;
    int pos0 = basep[c0v] + __popc(m0[c0v] & lt);
    bp[pos0] = (ushort)(v0 & 511);
    if (lane < 8) {
        int pos1 = basep[c1v] + __popc(m0[c1v]) + __popc(m1[c1v] & lt);
        bp[pos1] = (ushort)(v1 & 511);
    }
    if (lane == 0)
        g_bcnt4[l] = (uint)cnt[0] | ((uint)cnt[1] << 8) | ((uint)cnt[2] << 16) | ((uint)cnt[3] << 24);
}

// ---------------- K1: lane-pair-per-query, 512-row chunks (divergence 1.5x) ----------------
// block = (bh, 256-query panel), 512 threads. thread = (query, half-of-D).
#define SMEM1_BYTES (KCH4*D*4 + LCH*S*2)   // 131072 + 20480 = 151552

__global__ void __launch_bounds__(512, 1) k1_p4(const float* __restrict__ Qg,
                                                const float* __restrict__ Kg) {
    int bh = blockIdx.x >> 3, lch = blockIdx.x & 7;
    int b = bh >> 3, h = bh & 7;
    int l0 = lch * LCH;
    int t = threadIdx.x, lane = t & 31;
    int sub = t & 1;            // which half of D
    int q   = t >> 1;           // query 0..255
    int qi  = lane >> 1;        // query-in-warp 0..15
    extern __shared__ float sm[];
    float4* Ks4 = (float4*)sm;                     // 512 rows x 16 float4
    ushort* sIdx = (ushort*)(sm + KCH4*D);         // 256 x 40 ushort

    // per-thread column order: 8 float4 cols in own half; each 8-lane phase
    // covers 8 distinct 16B bank groups for ANY row set
    int offs[8];
    #pragma unroll
    for (int j = 0; j < 8; j++) offs[j] = sub*8 + ((j + qi + sub*4) & 7);

    // ---- stage Q panel into Ks4 (coalesced), idx ushorts into sIdx ----
    for (int e = t; e < LCH*16; e += 512) {
        int i = e >> 4, c4 = e & 15;
        Ks4[e] = __ldg((const float4*)(Qg + ((size_t)(b*L + l0 + i)*H + h)*D) + c4);
    }
    uint* si32 = (uint*)sIdx;
    for (int e = t; e < LCH*S/2; e += 512)
        si32[e] = g_bidxw[l0*(S/2) + e];
    __syncthreads();

    // own half-row of Q -> 16 regs (pre-rotated to match offs[])
    ull q0[8], q1[8];
    #pragma unroll
    for (int j = 0; j < 8; j++) {
        float4 v = Ks4[q*16 + offs[j]];
        q0[j] = pk2(v.x, v.y);
        q1[j] = pk2(v.z, v.w);
    }
    uint cw = g_bcnt4[l0 + q];
    __syncthreads();

    unsigned pmask = 3u << (lane & ~1);   // the lane pair (always convergent)
    ull z = pk2(0.f, 0.f);
    float lmax = NEG_INF, lsum = 0.f;
    int p0 = q * S;

    for (int c = 0; c < NCH4; c++) {
        // stage 512-row K chunk (coalesced)
        const float* Kbase = Kg + (size_t)(b*L + c*KCH4)*(H*D) + h*D;
        for (int e = t; e < KCH4*16; e += 512) {
            int kk = e >> 4, c4 = e & 15;
            Ks4[e] = __ldg((const float4*)(Kbase + (size_t)kk*(H*D)) + c4);
        }
        __syncthreads();

        int cnt = (int)((cw >> (c*8)) & 255u);
        if (cnt) {
            int row = sIdx[p0];
            for (int j = 0; j < cnt; j++) {
                int jn = (j + 1 < cnt) ? j + 1 : j;
                int rown = sIdx[p0 + jn];              // prefetch next index
                const float4* kp = Ks4 + row*16;
                ull a0 = z, a1 = z;
                #pragma unroll
                for (int jj = 0; jj < 8; jj++) {
                    float4 kv = kp[offs[jj]];
                    a0 = fma2_(q0[jj], pk2(kv.x, kv.y), a0);
                    a1 = fma2_(q1[jj], pk2(kv.z, kv.w), a1);
                }
                a0 = add2_(a0, a1);
                float lo, hi; upk2(a0, lo, hi);
                float pdot = lo + hi;
                pdot += __shfl_xor_sync(pmask, pdot, 1);  // combine the two halves
                lmax = fmaxf(lmax, pdot);
                lsum += pdot;
                row = rown;
            }
        }
        p0 += cnt;
        __syncthreads();
    }

    if (sub == 0)
        g_M[bh*L + l0 + q] = lmax - lsum * (1.0f / S);
}

// ---------------- K2: two-level top-U (warp-local lists, then merge) ----------------
__global__ void __launch_bounds__(256) k2_topk() {
    __shared__ float sv[L];
    __shared__ float wvs[8*U];
    __shared__ int   wis[8*U];
    int bh = blockIdx.x, tid = threadIdx.x;
    int lane = tid & 31, w = tid >> 5;
    for (int i = tid; i < L; i += 256) sv[i] = g_M[bh*L + i];
    __syncthreads();

    int base = w*256 + lane;
    float v[8];
    #pragma unroll
    for (int t = 0; t < 8; t++) v[t] = sv[base + t*32];
    for (int it = 0; it < U; it++) {
        float bv = v[0]; int bt = 0;
        #pragma unroll
        for (int t = 1; t < 8; t++)
            if (v[t] > bv) { bv = v[t]; bt = t; }
        int bi = base + bt*32;
        #pragma unroll
        for (int o = 16; o; o >>= 1) {
            float ov = __shfl_xor_sync(0xffffffffu, bv, o);
            int   oi = __shfl_xor_sync(0xffffffffu, bi, o);
            if (ov > bv || (ov == bv && oi < bi)) { bv = ov; bi = oi; }
        }
        int rel = bi - w*256;
        if ((rel & 31) == lane) v[rel >> 5] = NEG_INF;
        if (lane == 0) { wvs[w*U + it] = bv; wis[w*U + it] = bi; }
    }
    __syncthreads();

    if (w == 0) {
        float cv[10]; int ci[10];
        #pragma unroll
        for (int r = 0; r < 10; r++) { cv[r] = wvs[lane + 32*r]; ci[r] = wis[lane + 32*r]; }
        for (int it = 0; it < U; it++) {
            float bv = cv[0]; int bi = ci[0];
            #pragma unroll
            for (int r = 1; r < 10; r++)
                if (cv[r] > bv || (cv[r] == bv && ci[r] < bi)) { bv = cv[r]; bi = ci[r]; }
            #pragma unroll
            for (int o = 16; o; o >>= 1) {
                float ov = __shfl_xor_sync(0xffffffffu, bv, o);
                int   oi = __shfl_xor_sync(0xffffffffu, bi, o);
                if (ov > bv || (ov == bv && oi < bi)) { bv = ov; bi = oi; }
            }
            if (lane == 0) g_Mtop[bh*U + it] = bi;
            #pragma unroll
            for (int r = 0; r < 10; r++)
                if (ci[r] == bi) cv[r] = NEG_INF;
        }
    }
}

// ---------------- K3: partial V sums over L-chunks ----------------
__global__ void __launch_bounds__(256) k3_vsum(const float* __restrict__ Vg) {
    int bh = blockIdx.x >> 3, sp = blockIdx.x & 7;
    int b = bh >> 3, h = bh & 7;
    int d  = threadIdx.x & 63;
    int lg = threadIdx.x >> 6;
    const float* base = Vg + (size_t)b*L*(H*D) + h*D + d;
    int l0 = sp*CHUNK + lg;
    float a0 = 0.f, a1 = 0.f;
    #pragma unroll 8
    for (int i = 0; i < CHUNK/8; i++) {
        a0 += base[(size_t)(l0 + i*8    ) * (H*D)];
        a1 += base[(size_t)(l0 + i*8 + 4) * (H*D)];
    }
    __shared__ float red[4][64];
    red[lg][d] = a0 + a1;
    __syncthreads();
    if (threadIdx.x < 64)
        g_Vpart[(bh*SPLIT + sp)*D + threadIdx.x] =
            red[0][threadIdx.x] + red[1][threadIdx.x] + red[2][threadIdx.x] + red[3][threadIdx.x];
}

// ---------------- K4: broadcast V-mean into full output ----------------
__global__ void __launch_bounds__(256) k4_fill(float* __restrict__ out) {
    int b  = blockIdx.x >> 6;
    int r0 = (blockIdx.x & 63) * 32;
    __shared__ __align__(16) float vec[512];
    int tid = threadIdx.x;
    for (int j = tid; j < 512; j += 256) {
        int h = j >> 6, d = j & 63;
        float s = 0.f;
        #pragma unroll
        for (int sp = 0; sp < SPLIT; sp++)
            s += g_Vpart[((b*H + h)*SPLIT + sp)*D + d];
        vec[j] = s * (1.0f / L);
    }
    __syncthreads();
    float4* o4 = (float4*)(out + (size_t)(b*L + r0) * (H*D));
    const float4* v4 = (const float4*)vec;
    for (int e = tid; e < 32*128; e += 256) {
        int r = e >> 7, c = e & 127;
        o4[r*128 + c] = v4[c];
    }
}

// ---------------- K5: split-K sparse attention, f32x2, Qs aliased into Sc ----------------
#define SCW 264
#define SM5_KS 0
#define SM5_SC 16384
#define SMEM5_BYTES ((16384 + U*SCW) * 4)   // 107776

__global__ void __launch_bounds__(256, 2) k5_attn(const float* __restrict__ Qg,
                                                  const float* __restrict__ Kg,
                                                  const float* __restrict__ Vg) {
    int bh = blockIdx.x >> 3, sp = blockIdx.x & 7;
    int b = bh >> 3, h = bh & 7;
    int tid = threadIdx.x;
    extern __shared__ float sm[];
    float2* Ks2 = (float2*)(sm + SM5_KS);
    float*  Sc  = sm + SM5_SC;
    float*  Qs  = sm + SM5_SC;             // aliased: Qs dead after phase 1
    float2* Qs2 = (float2*)Qs;
    __shared__ int topq[U];

    if (tid < U) topq[tid] = g_Mtop[bh*U + tid];
    __syncthreads();

    for (int e = tid; e < U*D; e += 256) {
        int i = e >> 6, d = e & 63;
        Qs[e] = Qg[((size_t)(b*L + topq[i])*H + h)*D + d];
    }
    const float* Kbase = Kg + (size_t)(b*L + sp*CHUNK)*(H*D) + h*D;
    for (int e = tid; e < CHUNK*D/2; e += 256) {
        int kk = e >> 5, c2 = e & 31;
        Ks2[kk*32 + (c2 ^ (kk >> 3))] = *(const float2*)(Kbase + (size_t)kk*(H*D) + c2*2);
    }
    __syncthreads();

    int qg = tid >> 5, kg = tid & 31;
    ull z2 = pk2(0.f, 0.f);
    ull acc2[5][8];
    #pragma unroll
    for (int i = 0; i < 5; i++)
        #pragma unroll
        for (int j = 0; j < 8; j++) acc2[i][j] = z2;

    #pragma unroll 2
    for (int dd = 0; dd < 32; dd++) {
        ull qv[5], kv[8];
        #pragma unroll
        for (int i = 0; i < 5; i++) { float2 tq = Qs2[(qg*5 + i)*32 + dd]; qv[i] = pk2(tq.x, tq.y); }
        #pragma unroll
        for (int j = 0; j < 8; j++) { float2 tk = Ks2[(kg*8 + j)*32 + (dd ^ kg)]; kv[j] = pk2(tk.x, tk.y); }
        #pragma unroll
        for (int i = 0; i < 5; i++)
            #pragma unroll
            for (int j = 0; j < 8; j++) acc2[i][j] = fma2_(qv[i], kv[j], acc2[i][j]);
    }
    __syncthreads();   // ALL Qs/Ks reads done before Sc (aliased) writes & V load

    #pragma unroll
    for (int i = 0; i < 5; i++) {
        int q = qg*5 + i;
        float s[8];
        #pragma unroll
        for (int j = 0; j < 8; j++) { float lo, hi; upk2(acc2[i][j], lo, hi); s[j] = (lo + hi) * 0.125f; }
        float4* dst = (float4*)(Sc + q*SCW + kg*8);
        dst[0] = make_float4(s[0], s[1], s[2], s[3]);
        dst[1] = make_float4(s[4], s[5], s[6], s[7]);
    }
    const float* Vbase = Vg + (size_t)(b*L + sp*CHUNK)*(H*D) + h*D;
    for (int e = tid; e < CHUNK*D/2; e += 256) {
        int kk = e >> 5, c2 = e & 31;
        Ks2[kk*32 + (c2 ^ (kk >> 3))] = *(const float2*)(Vbase + (size_t)kk*(H*D) + c2*2);
    }
    __syncthreads();

    int lane = tid & 31;
    #pragma unroll
    for (int i = 0; i < 5; i++) {
        int q = qg*5 + i;
        float vals[8];
        float mv = NEG_INF;
        #pragma unroll
        for (int t = 0; t < 8; t++) {
            vals[t] = Sc[q*SCW + lane + t*32];
            mv = fmaxf(mv, vals[t]);
        }
        #pragma unroll
        for (int o = 16; o; o >>= 1) mv = fmaxf(mv, __shfl_xor_sync(0xffffffffu, mv, o));
        float ssum = 0.f;
        #pragma unroll
        for (int t = 0; t < 8; t++) {
            float ev = __expf(vals[t] - mv);
            Sc[q*SCW + lane + t*32] = ev;
            ssum += ev;
        }
        #pragma unroll
        for (int o = 16; o; o >>= 1) ssum += __shfl_xor_sync(0xffffffffu, ssum, o);
        if (lane == 0) {
            g_pm[(bh*SPLIT + sp)*U + q] = mv;
            g_pl[(bh*SPLIT + sp)*U + q] = ssum;
        }
    }
    __syncthreads();

    int kr  = tid >> 6;
    int r   = tid & 63;
    int qg2 = r >> 3, dg = r & 7;
    ull facc[5][4];
    #pragma unroll
    for (int i = 0; i < 5; i++)
        #pragma unroll
        for (int j = 0; j < 4; j++) facc[i][j] = z2;

    #pragma unroll 2
    for (int kl = 0; kl < 64; kl++) {
        int kk = kr*64 + kl;
        ull pv2[5], vv[4];
        #pragma unroll
        for (int i = 0; i < 5; i++) {
            float p = Sc[(qg2*5 + i)*SCW + kk];
            pv2[i] = pk2(p, p);
        }
        int sw = kk >> 3;
        #pragma unroll
        for (int j = 0; j < 4; j++) {
            float2 tv = Ks2[kk*32 + ((dg*4 + j) ^ sw)];
            vv[j] = pk2(tv.x, tv.y);
        }
        #pragma unroll
        for (int i = 0; i < 5; i++)
            #pragma unroll
            for (int j = 0; j < 4; j++) facc[i][j] = fma2_(pv2[i], vv[j], facc[i][j]);
    }
    __syncthreads();
    float2* Scr = (float2*)Sc;
    #pragma unroll
    for (int i = 0; i < 5; i++) {
        int q = qg2*5 + i;
        #pragma unroll
        for (int j = 0; j < 4; j++) {
            float lo, hi; upk2(facc[i][j], lo, hi);
            Scr[kr*1280 + q*32 + dg*4 + j] = make_float2(lo, hi);
        }
    }
    __syncthreads();
    float2* pO2 = g_pO2 + (size_t)(bh*SPLIT + sp)*U*D/2;
    for (int e = tid; e < U*D/2; e += 256) {
        float2 a = Scr[e], b2 = Scr[1280 + e], c = Scr[2560 + e], d2 = Scr[3840 + e];
        pO2[e] = make_float2(a.x + b2.x + c.x + d2.x, a.y + b2.y + c.y + d2.y);
    }
}

// ---------------- K6: combine splits + scatter to output ----------------
__global__ void __launch_bounds__(256) k6_combine(float* __restrict__ out) {
    int bh = blockIdx.x;
    int b = bh >> 3, h = bh & 7;
    __shared__ float w[U*SPLIT];
    __shared__ int topq[U];
    int tid = threadIdx.x;
    const float* gpO = (const float*)g_pO2;
    if (tid < U) {
        topq[tid] = g_Mtop[bh*U + tid];
        float pm_[SPLIT], pl_[SPLIT];
        float m = NEG_INF;
        #pragma unroll
        for (int sp = 0; sp < SPLIT; sp++) {
            pm_[sp] = g_pm[(bh*SPLIT + sp)*U + tid];
            pl_[sp] = g_pl[(bh*SPLIT + sp)*U + tid];
            m = fmaxf(m, pm_[sp]);
        }
        float denom = 0.f, e_[SPLIT];
        #pragma unroll
        for (int sp = 0; sp < SPLIT; sp++) {
            e_[sp] = __expf(pm_[sp] - m);
            denom += pl_[sp] * e_[sp];
        }
        float inv = 1.0f / denom;
        #pragma unroll
        for (int sp = 0; sp < SPLIT; sp++) w[tid*SPLIT + sp] = e_[sp] * inv;
    }
    __syncthreads();
    for (int e = tid; e < U*D; e += 256) {
        int q = e >> 6, d = e & 63;
        float s = 0.f;
        #pragma unroll
        for (int sp = 0; sp < SPLIT; sp++)
            s += gpO[((size_t)(bh*SPLIT + sp)*U + q)*D + d] * w[q*SPLIT + sp];
        out[((size_t)(b*L + topq[q])*H + h)*D + d] = s;
    }
}

// ---------------- launch ----------------
extern "C" void kernel_launch(void* const* d_in, const int* in_sizes, int n_in,
                              void* d_out, int out_size) {
    const float* Q   = (const float*)d_in[0];
    const float* K   = (const float*)d_in[1];
    const float* V   = (const float*)d_in[2];
    const int*  idxs = (const int*)d_in[3];
    float* out = (float*)d_out;

    cudaFuncSetAttribute(k1_p4,   cudaFuncAttributeMaxDynamicSharedMemorySize, SMEM1_BYTES);
    cudaFuncSetAttribute(k5_attn, cudaFuncAttributeMaxDynamicSharedMemorySize, SMEM5_BYTES);

    // k1 stays 4th launch for the ncu capture slot
    k0_bucket <<<L/8,       256>>>(idxs);
    k3_vsum   <<<NBH*SPLIT, 256>>>(V);
    k4_fill   <<<B*64,      256>>>(out);
    k1_p4     <<<NBH*8,     512, SMEM1_BYTES>>>(Q, K);
    k2_topk   <<<NBH,       256>>>();
    k5_attn   <<<NBH*SPLIT, 256, SMEM5_BYTES>>>(Q, K, V);
    k6_combine<<<NBH,       256>>>(out);
}

// round 13
// speedup vs baseline: 1.0471x; 1.0270x over previous
#include <cuda_runtime.h>

#define B 8
#define L 2048
#define H 8
#define D 64
#define S 40
#define U 40
#define NBH (B*H)
#define SPLIT 8
#define CHUNK (L/SPLIT)   // 256 (K5 key chunk)
#define KCH 256           // K1: key rows per chunk
#define NCH 8             // K1: key chunks
#define LCH 256           // K1: queries per block
#define NEG_INF (-3.4e38f)

typedef unsigned long long ull;
typedef unsigned int uint;

// ---------------- f32x2 helpers ----------------
__device__ __forceinline__ ull pk2(float a, float b) {
    ull r; asm("mov.b64 %0,{%1,%2};" : "=l"(r) : "f"(a), "f"(b)); return r;
}
__device__ __forceinline__ void upk2(ull v, float& a, float& b) {
    asm("mov.b64 {%0,%1},%2;" : "=f"(a), "=f"(b) : "l"(v));
}
__device__ __forceinline__ ull fma2_(ull a, ull b, ull c) {
    ull d; asm("fma.rn.f32x2 %0,%1,%2,%3;" : "=l"(d) : "l"(a), "l"(b), "l"(c)); return d;
}
__device__ __forceinline__ ull add2_(ull a, ull b) {
    ull d; asm("add.rn.f32x2 %0,%1,%2;" : "=l"(d) : "l"(a), "l"(b)); return d;
}

// ---------------- scratch (device globals; no allocation) ----------------
__device__ uint     g_bidxw[L*S/4];       // per-l sample rows as bytes, sorted by chunk
__device__ uint     g_bcntw[L*2];         // per-l 8 chunk counts as bytes
__device__ float    g_M[NBH*L];           // sparsity metric
__device__ int      g_Mtop[NBH*U];        // top-U query indices per bh
__device__ float    g_Vpart[NBH*SPLIT*D]; // partial V sums
__device__ float2   g_pO2[NBH*SPLIT*U*D/2]; // split attention partial outputs
__device__ float    g_pm[NBH*SPLIT*U];    // split local max
__device__ float    g_pl[NBH*SPLIT*U];    // split local sum-exp

// ---------------- K0: warp-per-query ballot bucketing (8 buckets, byte rows) ----------------
__global__ void __launch_bounds__(256) k0_bucket(const int* __restrict__ idxs) {
    int w = threadIdx.x >> 5, lane = threadIdx.x & 31;
    int l = blockIdx.x * 8 + w;                     // 256 blocks x 8 warps = 2048
    const int* p = idxs + l * S;
    int v0 = p[lane];
    int c0v = v0 >> 8;
    int v1 = 0, c1v = -1;
    if (lane < 8) { v1 = p[32 + lane]; c1v = v1 >> 8; }
    unsigned m0[NCH], m1[NCH];
    int cnt[NCH];
    #pragma unroll
    for (int cc = 0; cc < NCH; cc++) {
        m0[cc] = __ballot_sync(0xffffffffu, c0v == cc);
        m1[cc] = __ballot_sync(0xffffffffu, c1v == cc);
        cnt[cc] = __popc(m0[cc]) + __popc(m1[cc]);
    }
    int basep[NCH];
    int run = 0;
    #pragma unroll
    for (int cc = 0; cc < NCH; cc++) { basep[cc] = run; run += cnt[cc]; }
    unsigned lt = (1u << lane) - 1u;
    unsigned char* bp = (unsigned char*)g_bidxw + l*S;
    int pos0 = basep[c0v] + __popc(m0[c0v] & lt);
    bp[pos0] = (unsigned char)(v0 & 255);
    if (lane < 8) {
        int pos1 = basep[c1v] + __popc(m0[c1v]) + __popc(m1[c1v] & lt);
        bp[pos1] = (unsigned char)(v1 & 255);
    }
    if (lane == 0) {
        g_bcntw[l*2    ] = (uint)cnt[0] | ((uint)cnt[1] << 8) | ((uint)cnt[2] << 16) | ((uint)cnt[3] << 24);
        g_bcntw[l*2 + 1] = (uint)cnt[4] | ((uint)cnt[5] << 8) | ((uint)cnt[6] << 16) | ((uint)cnt[7] << 24);
    }
}

// ---------------- K1: thread-per-query, Q in registers, ILP-2 over sample pairs ----------------
#define SMEM1_BYTES (KCH*D*4 + LCH*S)   // 65536 + 10240 = 75776

__global__ void __launch_bounds__(256, 2) k1_reg(const float* __restrict__ Qg,
                                                 const float* __restrict__ Kg) {
    int bh = blockIdx.x >> 3, lch = blockIdx.x & 7;
    int b = bh >> 3, h = bh & 7;
    int l0 = lch * LCH;
    int t = threadIdx.x, lane = t & 31;
    extern __shared__ float sm[];
    float4* Ks4 = (float4*)sm;                           // 256 rows x 16 float4
    unsigned char* sByte = (unsigned char*)(sm + KCH*D); // 256 x 40 bytes

    int offs[16];
    #pragma unroll
    for (int j = 0; j < 16; j++) offs[j] = (lane + j) & 15;

    // ---- stage Q panel into Ks4 (coalesced), idx bytes into sByte ----
    for (int e = t; e < LCH*16; e += 256) {
        int i = e >> 4, c4 = e & 15;
        Ks4[e] = __ldg((const float4*)(Qg + ((size_t)(b*L + l0 + i)*H + h)*D) + c4);
    }
    uint* sb32 = (uint*)sByte;
    for (int e = t; e < LCH*(S/4); e += 256)
        sb32[e] = g_bidxw[l0*(S/4) + e];
    __syncthreads();

    ull q0[16], q1[16];
    #pragma unroll
    for (int j = 0; j < 16; j++) {
        float4 v = Ks4[t*16 + offs[j]];
        q0[j] = pk2(v.x, v.y);
        q1[j] = pk2(v.z, v.w);
    }
    uint cw0 = g_bcntw[(l0 + t)*2];
    uint cw1 = g_bcntw[(l0 + t)*2 + 1];
    __syncthreads();

    ull z = pk2(0.f, 0.f);
    float lmax = NEG_INF, lsum = 0.f;
    int p0 = t * S;

    for (int c = 0; c < NCH; c++) {
        const float* Kbase = Kg + (size_t)(b*L + c*KCH)*(H*D) + h*D;
        for (int e = t; e < KCH*16; e += 256) {
            int kk = e >> 4, c4 = e & 15;
            Ks4[e] = __ldg((const float4*)(Kbase + (size_t)kk*(H*D)) + c4);
        }
        __syncthreads();

        int cnt = (c < 4) ? (int)((cw0 >> (c*8)) & 255u)
                          : (int)((cw1 >> ((c-4)*8)) & 255u);
        int j = 0;
        // ---- ILP-2: two independent sample dots in flight ----
        for (; j + 2 <= cnt; j += 2) {
            int rowA = sByte[p0 + j];
            int rowB = sByte[p0 + j + 1];
            const float4* kpA = Ks4 + rowA*16;
            const float4* kpB = Ks4 + rowB*16;
            ull a0 = z, a1 = z, b0 = z, b1 = z;
            #pragma unroll
            for (int g = 0; g < 4; g++) {
                float4 A0 = kpA[offs[4*g + 0]];
                float4 A1 = kpA[offs[4*g + 1]];
                float4 A2 = kpA[offs[4*g + 2]];
                float4 A3 = kpA[offs[4*g + 3]];
                a0 = fma2_(q0[4*g + 0], pk2(A0.x, A0.y), a0);
                a1 = fma2_(q1[4*g + 0], pk2(A0.z, A0.w), a1);
                a0 = fma2_(q0[4*g + 1], pk2(A1.x, A1.y), a0);
                a1 = fma2_(q1[4*g + 1], pk2(A1.z, A1.w), a1);
                a0 = fma2_(q0[4*g + 2], pk2(A2.x, A2.y), a0);
                a1 = fma2_(q1[4*g + 2], pk2(A2.z, A2.w), a1);
                a0 = fma2_(q0[4*g + 3], pk2(A3.x, A3.y), a0);
                a1 = fma2_(q1[4*g + 3], pk2(A3.z, A3.w), a1);
                float4 B0 = kpB[offs[4*g + 0]];
                float4 B1 = kpB[offs[4*g + 1]];
                float4 B2 = kpB[offs[4*g + 2]];
                float4 B3 = kpB[offs[4*g + 3]];
                b0 = fma2_(q0[4*g + 0], pk2(B0.x, B0.y), b0);
                b1 = fma2_(q1[4*g + 0], pk2(B0.z, B0.w), b1);
                b0 = fma2_(q0[4*g + 1], pk2(B1.x, B1.y), b0);
                b1 = fma2_(q1[4*g + 1], pk2(B1.z, B1.w), b1);
                b0 = fma2_(q0[4*g + 2], pk2(B2.x, B2.y), b0);
                b1 = fma2_(q1[4*g + 2], pk2(B2.z, B2.w), b1);
                b0 = fma2_(q0[4*g + 3], pk2(B3.x, B3.y), b0);
                b1 = fma2_(q1[4*g + 3], pk2(B3.z, B3.w), b1);
            }
            a0 = add2_(a0, a1);
            b0 = add2_(b0, b1);
            float la, ha, lb, hb;
            upk2(a0, la, ha);
            upk2(b0, lb, hb);
            float pA = la + ha;
            float pB = lb + hb;
            lmax = fmaxf(lmax, fmaxf(pA, pB));
            lsum += (pA + pB);
        }
        if (j < cnt) {   // odd tail: single task
            int row = sByte[p0 + j];
            const float4* kp = Ks4 + row*16;
            ull a0 = z, a1 = z;
            #pragma unroll
            for (int g = 0; g < 4; g++) {
                float4 A0 = kp[offs[4*g + 0]];
                float4 A1 = kp[offs[4*g + 1]];
                float4 A2 = kp[offs[4*g + 2]];
                float4 A3 = kp[offs[4*g + 3]];
                a0 = fma2_(q0[4*g + 0], pk2(A0.x, A0.y), a0);
                a1 = fma2_(q1[4*g + 0], pk2(A0.z, A0.w), a1);
                a0 = fma2_(q0[4*g + 1], pk2(A1.x, A1.y), a0);
                a1 = fma2_(q1[4*g + 1], pk2(A1.z, A1.w), a1);
                a0 = fma2_(q0[4*g + 2], pk2(A2.x, A2.y), a0);
                a1 = fma2_(q1[4*g + 2], pk2(A2.z, A2.w), a1);
                a0 = fma2_(q0[4*g + 3], pk2(A3.x, A3.y), a0);
                a1 = fma2_(q1[4*g + 3], pk2(A3.z, A3.w), a1);
            }
            a0 = add2_(a0, a1);
            float lo, hi; upk2(a0, lo, hi);
            float pA = lo + hi;
            lmax = fmaxf(lmax, pA);
            lsum += pA;
        }
        p0 += cnt;
        __syncthreads();
    }

    g_M[bh*L + l0 + t] = lmax - lsum * (1.0f / S);
}

// ---------------- K2: two-level top-U (warp-local lists, then merge) ----------------
__global__ void __launch_bounds__(256) k2_topk() {
    __shared__ float sv[L];
    __shared__ float wvs[8*U];
    __shared__ int   wis[8*U];
    int bh = blockIdx.x, tid = threadIdx.x;
    int lane = tid & 31, w = tid >> 5;
    for (int i = tid; i < L; i += 256) sv[i] = g_M[bh*L + i];
    __syncthreads();

    int base = w*256 + lane;
    float v[8];
    #pragma unroll
    for (int t = 0; t < 8; t++) v[t] = sv[base + t*32];
    for (int it = 0; it < U; it++) {
        float bv = v[0]; int bt = 0;
        #pragma unroll
        for (int t = 1; t < 8; t++)
            if (v[t] > bv) { bv = v[t]; bt = t; }
        int bi = base + bt*32;
        #pragma unroll
        for (int o = 16; o; o >>= 1) {
            float ov = __shfl_xor_sync(0xffffffffu, bv, o);
            int   oi = __shfl_xor_sync(0xffffffffu, bi, o);
            if (ov > bv || (ov == bv && oi < bi)) { bv = ov; bi = oi; }
        }
        int rel = bi - w*256;
        if ((rel & 31) == lane) v[rel >> 5] = NEG_INF;
        if (lane == 0) { wvs[w*U + it] = bv; wis[w*U + it] = bi; }
    }
    __syncthreads();

    if (w == 0) {
        float cv[10]; int ci[10];
        #pragma unroll
        for (int r = 0; r < 10; r++) { cv[r] = wvs[lane + 32*r]; ci[r] = wis[lane + 32*r]; }
        for (int it = 0; it < U; it++) {
            float bv = cv[0]; int bi = ci[0];
            #pragma unroll
            for (int r = 1; r < 10; r++)
                if (cv[r] > bv || (cv[r] == bv && ci[r] < bi)) { bv = cv[r]; bi = ci[r]; }
            #pragma unroll
            for (int o = 16; o; o >>= 1) {
                float ov = __shfl_xor_sync(0xffffffffu, bv, o);
                int   oi = __shfl_xor_sync(0xffffffffu, bi, o);
                if (ov > bv || (ov == bv && oi < bi)) { bv = ov; bi = oi; }
            }
            if (lane == 0) g_Mtop[bh*U + it] = bi;
            #pragma unroll
            for (int r = 0; r < 10; r++)
                if (ci[r] == bi) cv[r] = NEG_INF;
        }
    }
}

// ---------------- K3: partial V sums over L-chunks ----------------
__global__ void __launch_bounds__(256) k3_vsum(const float* __restrict__ Vg) {
    int bh = blockIdx.x >> 3, sp = blockIdx.x & 7;
    int b = bh >> 3, h = bh & 7;
    int d  = threadIdx.x & 63;
    int lg = threadIdx.x >> 6;
    const float* base = Vg + (size_t)b*L*(H*D) + h*D + d;
    int l0 = sp*CHUNK + lg;
    float a0 = 0.f, a1 = 0.f;
    #pragma unroll 8
    for (int i = 0; i < CHUNK/8; i++) {
        a0 += base[(size_t)(l0 + i*8    ) * (H*D)];
        a1 += base[(size_t)(l0 + i*8 + 4) * (H*D)];
    }
    __shared__ float red[4][64];
    red[lg][d] = a0 + a1;
    __syncthreads();
    if (threadIdx.x < 64)
        g_Vpart[(bh*SPLIT + sp)*D + threadIdx.x] =
            red[0][threadIdx.x] + red[1][threadIdx.x] + red[2][threadIdx.x] + red[3][threadIdx.x];
}

// ---------------- K4: broadcast V-mean into full output ----------------
__global__ void __launch_bounds__(256) k4_fill(float* __restrict__ out) {
    int b  = blockIdx.x >> 6;
    int r0 = (blockIdx.x & 63) * 32;
    __shared__ __align__(16) float vec[512];
    int tid = threadIdx.x;
    for (int j = tid; j < 512; j += 256) {
        int h = j >> 6, d = j & 63;
        float s = 0.f;
        #pragma unroll
        for (int sp = 0; sp < SPLIT; sp++)
            s += g_Vpart[((b*H + h)*SPLIT + sp)*D + d];
        vec[j] = s * (1.0f / L);
    }
    __syncthreads();
    float4* o4 = (float4*)(out + (size_t)(b*L + r0) * (H*D));
    const float4* v4 = (const float4*)vec;
    for (int e = tid; e < 32*128; e += 256) {
        int r = e >> 7, c = e & 127;
        o4[r*128 + c] = v4[c];
    }
}

// ---------------- K5: split-K sparse attention, f32x2, Qs aliased into Sc ----------------
#define SCW 264
#define SM5_KS 0
#define SM5_SC 16384
#define SMEM5_BYTES ((16384 + U*SCW) * 4)   // 107776

__global__ void __launch_bounds__(256, 2) k5_attn(const float* __restrict__ Qg,
                                                  const float* __restrict__ Kg,
                                                  const float* __restrict__ Vg) {
    int bh = blockIdx.x >> 3, sp = blockIdx.x & 7;
    int b = bh >> 3, h = bh & 7;
    int tid = threadIdx.x;
    extern __shared__ float sm[];
    float2* Ks2 = (float2*)(sm + SM5_KS);
    float*  Sc  = sm + SM5_SC;
    float*  Qs  = sm + SM5_SC;             // aliased: Qs dead after phase 1
    float2* Qs2 = (float2*)Qs;
    __shared__ int topq[U];

    if (tid < U) topq[tid] = g_Mtop[bh*U + tid];
    __syncthreads();

    for (int e = tid; e < U*D; e += 256) {
        int i = e >> 6, d = e & 63;
        Qs[e] = Qg[((size_t)(b*L + topq[i])*H + h)*D + d];
    }
    const float* Kbase = Kg + (size_t)(b*L + sp*CHUNK)*(H*D) + h*D;
    for (int e = tid; e < CHUNK*D/2; e += 256) {
        int kk = e >> 5, c2 = e & 31;
        Ks2[kk*32 + (c2 ^ (kk >> 3))] = *(const float2*)(Kbase + (size_t)kk*(H*D) + c2*2);
    }
    __syncthreads();

    int qg = tid >> 5, kg = tid & 31;
    ull z2 = pk2(0.f, 0.f);
    ull acc2[5][8];
    #pragma unroll
    for (int i = 0; i < 5; i++)
        #pragma unroll
        for (int j = 0; j < 8; j++) acc2[i][j] = z2;

    #pragma unroll 2
    for (int dd = 0; dd < 32; dd++) {
        ull qv[5], kv[8];
        #pragma unroll
        for (int i = 0; i < 5; i++) { float2 tq = Qs2[(qg*5 + i)*32 + dd]; qv[i] = pk2(tq.x, tq.y); }
        #pragma unroll
        for (int j = 0; j < 8; j++) { float2 tk = Ks2[(kg*8 + j)*32 + (dd ^ kg)]; kv[j] = pk2(tk.x, tk.y); }
        #pragma unroll
        for (int i = 0; i < 5; i++)
            #pragma unroll
            for (int j = 0; j < 8; j++) acc2[i][j] = fma2_(qv[i], kv[j], acc2[i][j]);
    }
    __syncthreads();   // ALL Qs/Ks reads done before Sc (aliased) writes & V load

    #pragma unroll
    for (int i = 0; i < 5; i++) {
        int q = qg*5 + i;
        float s[8];
        #pragma unroll
        for (int j = 0; j < 8; j++) { float lo, hi; upk2(acc2[i][j], lo, hi); s[j] = (lo + hi) * 0.125f; }
        float4* dst = (float4*)(Sc + q*SCW + kg*8);
        dst[0] = make_float4(s[0], s[1], s[2], s[3]);
        dst[1] = make_float4(s[4], s[5], s[6], s[7]);
    }
    const float* Vbase = Vg + (size_t)(b*L + sp*CHUNK)*(H*D) + h*D;
    for (int e = tid; e < CHUNK*D/2; e += 256) {
        int kk = e >> 5, c2 = e & 31;
        Ks2[kk*32 + (c2 ^ (kk >> 3))] = *(const float2*)(Vbase + (size_t)kk*(H*D) + c2*2);
    }
    __syncthreads();

    int lane = tid & 31;
    #pragma unroll
    for (int i = 0; i < 5; i++) {
        int q = qg*5 + i;
        float vals[8];
        float mv = NEG_INF;
        #pragma unroll
        for (int t = 0; t < 8; t++) {
            vals[t] = Sc[q*SCW + lane + t*32];
            mv = fmaxf(mv, vals[t]);
        }
        #pragma unroll
        for (int o = 16; o; o >>= 1) mv = fmaxf(mv, __shfl_xor_sync(0xffffffffu, mv, o));
        float ssum = 0.f;
        #pragma unroll
        for (int t = 0; t < 8; t++) {
            float ev = __expf(vals[t] - mv);
            Sc[q*SCW + lane + t*32] = ev;
            ssum += ev;
        }
        #pragma unroll
        for (int o = 16; o; o >>= 1) ssum += __shfl_xor_sync(0xffffffffu, ssum, o);
        if (lane == 0) {
            g_pm[(bh*SPLIT + sp)*U + q] = mv;
            g_pl[(bh*SPLIT + sp)*U + q] = ssum;
        }
    }
    __syncthreads();

    int kr  = tid >> 6;
    int r   = tid & 63;
    int qg2 = r >> 3, dg = r & 7;
    ull facc[5][4];
    #pragma unroll
    for (int i = 0; i < 5; i++)
        #pragma unroll
        for (int j = 0; j < 4; j++) facc[i][j] = z2;

    #pragma unroll 2
    for (int kl = 0; kl < 64; kl++) {
        int kk = kr*64 + kl;
        ull pv2[5], vv[4];
        #pragma unroll
        for (int i = 0; i < 5; i++) {
            float p = Sc[(qg2*5 + i)*SCW + kk];
            pv2[i] = pk2(p, p);
        }
        int sw = kk >> 3;
        #pragma unroll
        for (int j = 0; j < 4; j++) {
            float2 tv = Ks2[kk*32 + ((dg*4 + j) ^ sw)];
            vv[j] = pk2(tv.x, tv.y);
        }
        #pragma unroll
        for (int i = 0; i < 5; i++)
            #pragma unroll
            for (int j = 0; j < 4; j++) facc[i][j] = fma2_(pv2[i], vv[j], facc[i][j]);
    }
    __syncthreads();
    float2* Scr = (float2*)Sc;
    #pragma unroll
    for (int i = 0; i < 5; i++) {
        int q = qg2*5 + i;
        #pragma unroll
        for (int j = 0; j < 4; j++) {
            float lo, hi; upk2(facc[i][j], lo, hi);
            Scr[kr*1280 + q*32 + dg*4 + j] = make_float2(lo, hi);
        }
    }
    __syncthreads();
    float2* pO2 = g_pO2 + (size_t)(bh*SPLIT + sp)*U*D/2;
    for (int e = tid; e < U*D/2; e += 256) {
        float2 a = Scr[e], b2 = Scr[1280 + e], c = Scr[2560 + e], d2 = Scr[3840 + e];
        pO2[e] = make_float2(a.x + b2.x + c.x + d2.x, a.y + b2.y + c.y + d2.y);
    }
}

// ---------------- K6: combine splits + scatter to output ----------------
__global__ void __launch_bounds__(256) k6_combine(float* __restrict__ out) {
    int bh = blockIdx.x;
    int b = bh >> 3, h = bh & 7;
    __shared__ float w[U*SPLIT];
    __shared__ int topq[U];
    int tid = threadIdx.x;
    const float* gpO = (const float*)g_pO2;
    if (tid < U) {
        topq[tid] = g_Mtop[bh*U + tid];
        float pm_[SPLIT], pl_[SPLIT];
        float m = NEG_INF;
        #pragma unroll
        for (int sp = 0; sp < SPLIT; sp++) {
            pm_[sp] = g_pm[(bh*SPLIT + sp)*U + tid];
            pl_[sp] = g_pl[(bh*SPLIT + sp)*U + tid];
            m = fmaxf(m, pm_[sp]);
        }
        float denom = 0.f, e_[SPLIT];
        #pragma unroll
        for (int sp = 0; sp < SPLIT; sp++) {
            e_[sp] = __expf(pm_[sp] - m);
            denom += pl_[sp] * e_[sp];
        }
        float inv = 1.0f / denom;
        #pragma unroll
        for (int sp = 0; sp < SPLIT; sp++) w[tid*SPLIT + sp] = e_[sp] * inv;
    }
    __syncthreads();
    for (int e = tid; e < U*D; e += 256) {
        int q = e >> 6, d = e & 63;
        float s = 0.f;
        #pragma unroll
        for (int sp = 0; sp < SPLIT; sp++)
            s += gpO[((size_t)(bh*SPLIT + sp)*U + q)*D + d] * w[q*SPLIT + sp];
        out[((size_t)(b*L + topq[q])*H + h)*D + d] = s;
    }
}

// ---------------- launch ----------------
extern "C" void kernel_launch(void* const* d_in, const int* in_sizes, int n_in,
                              void* d_out, int out_size) {
    const float* Q   = (const float*)d_in[0];
    const float* K   = (const float*)d_in[1];
    const float* V   = (const float*)d_in[2];
    const int*  idxs = (const int*)d_in[3];
    float* out = (float*)d_out;

    cudaFuncSetAttribute(k1_reg,  cudaFuncAttributeMaxDynamicSharedMemorySize, SMEM1_BYTES);
    cudaFuncSetAttribute(k5_attn, cudaFuncAttributeMaxDynamicSharedMemorySize, SMEM5_BYTES);

    // side stream for the independent V-mean chain (k3 -> k4), joined before k6
    cudaStream_t s2;
    cudaStreamCreateWithFlags(&s2, cudaStreamNonBlocking);
    cudaEvent_t ev1, ev2;
    cudaEventCreateWithFlags(&ev1, cudaEventDisableTiming);
    cudaEventCreateWithFlags(&ev2, cudaEventDisableTiming);

    cudaEventRecord(ev1, 0);
    cudaStreamWaitEvent(s2, ev1, 0);
    k3_vsum   <<<NBH*SPLIT, 256, 0, s2>>>(V);
    k4_fill   <<<B*64,      256, 0, s2>>>(out);
    cudaEventRecord(ev2, s2);

    k0_bucket <<<L/8,       256>>>(idxs);
    k1_reg    <<<NBH*8,     256, SMEM1_BYTES>>>(Q, K);
    k2_topk   <<<NBH,       256>>>();
    k5_attn   <<<NBH*SPLIT, 256, SMEM5_BYTES>>>(Q, K, V);

    cudaStreamWaitEvent(0, ev2, 0);
    k6_combine<<<NBH,       256>>>(out);
}

// round 15
// speedup vs baseline: 1.1237x; 1.0732x over previous
#include <cuda_runtime.h>

#define B 8
#define L 2048
#define H 8
#define D 64
#define S 40
#define U 40
#define NBH (B*H)
#define SPLIT 8
#define CHUNK (L/SPLIT)   // 256 (K5 key chunk)
#define KCH 256           // K1: key rows per chunk
#define NCH 8             // K1: key chunks
#define LCH1 512          // K1: queries per block
#define NEG_INF (-3.4e38f)

typedef unsigned long long ull;
typedef unsigned int uint;

// ---------------- f32x2 helpers ----------------
__device__ __forceinline__ ull pk2(float a, float b) {
    ull r; asm("mov.b64 %0,{%1,%2};" : "=l"(r) : "f"(a), "f"(b)); return r;
}
__device__ __forceinline__ void upk2(ull v, float& a, float& b) {
    asm("mov.b64 {%0,%1},%2;" : "=f"(a), "=f"(b) : "l"(v));
}
__device__ __forceinline__ ull fma2_(ull a, ull b, ull c) {
    ull d; asm("fma.rn.f32x2 %0,%1,%2,%3;" : "=l"(d) : "l"(a), "l"(b), "l"(c)); return d;
}
__device__ __forceinline__ ull add2_(ull a, ull b) {
    ull d; asm("add.rn.f32x2 %0,%1,%2;" : "=l"(d) : "l"(a), "l"(b)); return d;
}

// ---------------- scratch (device globals; no allocation) ----------------
__device__ uint     g_bidxw[L*S/4];       // per-l sample rows as bytes, sorted by chunk
__device__ uint     g_bcntw[L*2];         // per-l 8 chunk counts as bytes
__device__ float    g_M[NBH*L];           // sparsity metric
__device__ int      g_Mtop[NBH*U];        // top-U query indices per bh
__device__ float    g_Vpart[NBH*SPLIT*D]; // partial V sums
__device__ float2   g_pO2[NBH*SPLIT*U*D/2]; // split attention partial outputs
__device__ float    g_pm[NBH*SPLIT*U];    // split local max
__device__ float    g_pl[NBH*SPLIT*U];    // split local sum-exp

// ---------------- K0: warp-per-query ballot bucketing (8 buckets, byte rows) ----------------
__global__ void __launch_bounds__(256) k0_bucket(const int* __restrict__ idxs) {
    int w = threadIdx.x >> 5, lane = threadIdx.x & 31;
    int l = blockIdx.x * 8 + w;                     // 256 blocks x 8 warps = 2048
    const int* p = idxs + l * S;
    int v0 = p[lane];
    int c0v = v0 >> 8;
    int v1 = 0, c1v = -1;
    if (lane < 8) { v1 = p[32 + lane]; c1v = v1 >> 8; }
    unsigned m0[NCH], m1[NCH];
    int cnt[NCH];
    #pragma unroll
    for (int cc = 0; cc < NCH; cc++) {
        m0[cc] = __ballot_sync(0xffffffffu, c0v == cc);
        m1[cc] = __ballot_sync(0xffffffffu, c1v == cc);
        cnt[cc] = __popc(m0[cc]) + __popc(m1[cc]);
    }
    int basep[NCH];
    int run = 0;
    #pragma unroll
    for (int cc = 0; cc < NCH; cc++) { basep[cc] = run; run += cnt[cc]; }
    unsigned lt = (1u << lane) - 1u;
    unsigned char* bp = (unsigned char*)g_bidxw + l*S;
    int pos0 = basep[c0v] + __popc(m0[c0v] & lt);
    bp[pos0] = (unsigned char)(v0 & 255);
    if (lane < 8) {
        int pos1 = basep[c1v] + __popc(m0[c1v]) + __popc(m1[c1v] & lt);
        bp[pos1] = (unsigned char)(v1 & 255);
    }
    if (lane == 0) {
        g_bcntw[l*2    ] = (uint)cnt[0] | ((uint)cnt[1] << 8) | ((uint)cnt[2] << 16) | ((uint)cnt[3] << 24);
        g_bcntw[l*2 + 1] = (uint)cnt[4] | ((uint)cnt[5] << 8) | ((uint)cnt[6] << 16) | ((uint)cnt[7] << 24);
    }
}

// ---------------- K1: thread-per-query, cp.async double-buffered K chunks ----------------
// block = (bh, 512-query panel), 512 threads, occ 1 (16 warps/SM).
#define SMEM1_BYTES (2*KCH*D*4 + LCH1*S)   // 131072 + 20480 = 151552

__global__ void __launch_bounds__(512, 1) k1_db(const float* __restrict__ Qg,
                                                const float* __restrict__ Kg) {
    int bh = blockIdx.x >> 2, lch = blockIdx.x & 3;
    int b = bh >> 3, h = bh & 7;
    int l0 = lch * LCH1;
    int t = threadIdx.x, lane = t & 31;
    extern __shared__ float sm[];
    float4* Buf = (float4*)sm;                             // 2 x 4096 float4 (two K buffers)
    unsigned char* sByte = (unsigned char*)(sm + 2*KCH*D); // 512 x 40 bytes

    int offs[16];
    #pragma unroll
    for (int j = 0; j < 16; j++) offs[j] = (lane + j) & 15;

    // ---- bounce Q panel (512 rows) through both buffers; stage idx bytes ----
    for (int e = t; e < LCH1*16; e += 512) {
        int i = e >> 4, c4 = e & 15;
        Buf[e] = __ldg((const float4*)(Qg + ((size_t)(b*L + l0 + i)*H + h)*D) + c4);
    }
    uint* sb32 = (uint*)sByte;
    for (int e = t; e < LCH1*(S/4); e += 512)
        sb32[e] = g_bidxw[l0*(S/4) + e];
    __syncthreads();

    ull q0[16], q1[16];
    #pragma unroll
    for (int j = 0; j < 16; j++) {
        float4 v = Buf[t*16 + offs[j]];
        q0[j] = pk2(v.x, v.y);
        q1[j] = pk2(v.z, v.w);
    }
    uint cw0 = g_bcntw[(l0 + t)*2];
    uint cw1 = g_bcntw[(l0 + t)*2 + 1];
    __syncthreads();   // Q panel reads done; buffers free for K staging

    // prologue: async-stage chunk 0 into buffer 0
    {
        const float* Kbase = Kg + (size_t)(b*L + 0*KCH)*(H*D) + h*D;
        #pragma unroll
        for (int it = 0; it < 8; it++) {
            int e = t + it*512;
            int kk = e >> 4, c4 = e & 15;
            unsigned sa = (unsigned)__cvta_generic_to_shared(Buf + e);
            asm volatile("cp.async.ca.shared.global [%0], [%1], 16;"
                         :: "r"(sa), "l"(Kbase + (size_t)kk*(H*D) + c4*4));
        }
        asm volatile("cp.async.commit_group;");
    }

    ull z = pk2(0.f, 0.f);
    float lmax = NEG_INF, lsum = 0.f;
    int p0 = t * S;

    for (int c = 0; c < NCH; c++) {
        // prefetch next chunk into the other buffer
        if (c + 1 < NCH) {
            const float* Kn = Kg + (size_t)(b*L + (c+1)*KCH)*(H*D) + h*D;
            float4* dstn = Buf + ((c + 1) & 1) * 4096;
            #pragma unroll
            for (int it = 0; it < 8; it++) {
                int e = t + it*512;
                int kk = e >> 4, c4 = e & 15;
                unsigned sa = (unsigned)__cvta_generic_to_shared(dstn + e);
                asm volatile("cp.async.ca.shared.global [%0], [%1], 16;"
                             :: "r"(sa), "l"(Kn + (size_t)kk*(H*D) + c4*4));
            }
            asm volatile("cp.async.commit_group;");
            asm volatile("cp.async.wait_group 1;");
        } else {
            asm volatile("cp.async.wait_group 0;");
        }
        __syncthreads();   // chunk c visible to all

        const float4* Ks4 = Buf + (c & 1) * 4096;
        int cnt = (c < 4) ? (int)((cw0 >> (c*8)) & 255u)
                          : (int)((cw1 >> ((c-4)*8)) & 255u);
        int j = 0;
        for (; j + 2 <= cnt; j += 2) {          // ILP-2: two sample dots in flight
            int rowA = sByte[p0 + j];
            int rowB = sByte[p0 + j + 1];
            const float4* kpA = Ks4 + rowA*16;
            const float4* kpB = Ks4 + rowB*16;
            ull a0 = z, a1 = z, b0 = z, b1 = z;
            #pragma unroll
            for (int g = 0; g < 4; g++) {
                float4 A0 = kpA[offs[4*g + 0]];
                float4 A1 = kpA[offs[4*g + 1]];
                float4 A2 = kpA[offs[4*g + 2]];
                float4 A3 = kpA[offs[4*g + 3]];
                a0 = fma2_(q0[4*g + 0], pk2(A0.x, A0.y), a0);
                a1 = fma2_(q1[4*g + 0], pk2(A0.z, A0.w), a1);
                a0 = fma2_(q0[4*g + 1], pk2(A1.x, A1.y), a0);
                a1 = fma2_(q1[4*g + 1], pk2(A1.z, A1.w), a1);
                a0 = fma2_(q0[4*g + 2], pk2(A2.x, A2.y), a0);
                a1 = fma2_(q1[4*g + 2], pk2(A2.z, A2.w), a1);
                a0 = fma2_(q0[4*g + 3], pk2(A3.x, A3.y), a0);
                a1 = fma2_(q1[4*g + 3], pk2(A3.z, A3.w), a1);
                float4 B0 = kpB[offs[4*g + 0]];
                float4 B1 = kpB[offs[4*g + 1]];
                float4 B2 = kpB[offs[4*g + 2]];
                float4 B3 = kpB[offs[4*g + 3]];
                b0 = fma2_(q0[4*g + 0], pk2(B0.x, B0.y), b0);
                b1 = fma2_(q1[4*g + 0], pk2(B0.z, B0.w), b1);
                b0 = fma2_(q0[4*g + 1], pk2(B1.x, B1.y), b0);
                b1 = fma2_(q1[4*g + 1], pk2(B1.z, B1.w), b1);
                b0 = fma2_(q0[4*g + 2], pk2(B2.x, B2.y), b0);
                b1 = fma2_(q1[4*g + 2], pk2(B2.z, B2.w), b1);
                b0 = fma2_(q0[4*g + 3], pk2(B3.x, B3.y), b0);
                b1 = fma2_(q1[4*g + 3], pk2(B3.z, B3.w), b1);
            }
            a0 = add2_(a0, a1);
            b0 = add2_(b0, b1);
            float la, ha, lb, hb;
            upk2(a0, la, ha);
            upk2(b0, lb, hb);
            float pA = la + ha;
            float pB = lb + hb;
            lmax = fmaxf(lmax, fmaxf(pA, pB));
            lsum += (pA + pB);
        }
        if (j < cnt) {   // odd tail
            int row = sByte[p0 + j];
            const float4* kp = Ks4 + row*16;
            ull a0 = z, a1 = z;
            #pragma unroll
            for (int g = 0; g < 4; g++) {
                float4 A0 = kp[offs[4*g + 0]];
                float4 A1 = kp[offs[4*g + 1]];
                float4 A2 = kp[offs[4*g + 2]];
                float4 A3 = kp[offs[4*g + 3]];
                a0 = fma2_(q0[4*g + 0], pk2(A0.x, A0.y), a0);
                a1 = fma2_(q1[4*g + 0], pk2(A0.z, A0.w), a1);
                a0 = fma2_(q0[4*g + 1], pk2(A1.x, A1.y), a0);
                a1 = fma2_(q1[4*g + 1], pk2(A1.z, A1.w), a1);
                a0 = fma2_(q0[4*g + 2], pk2(A2.x, A2.y), a0);
                a1 = fma2_(q1[4*g + 2], pk2(A2.z, A2.w), a1);
                a0 = fma2_(q0[4*g + 3], pk2(A3.x, A3.y), a0);
                a1 = fma2_(q1[4*g + 3], pk2(A3.z, A3.w), a1);
            }
            a0 = add2_(a0, a1);
            float lo, hi; upk2(a0, lo, hi);
            float pA = lo + hi;
            lmax = fmaxf(lmax, pA);
            lsum += pA;
        }
        p0 += cnt;
        __syncthreads();   // buf[c&1] free for chunk c+2's prefetch
    }

    g_M[bh*L + l0 + t] = lmax - lsum * (1.0f / S);
}

// ---------------- K2: two-level top-U (warp-local lists, then merge) ----------------
__global__ void __launch_bounds__(256) k2_topk() {
    __shared__ float sv[L];
    __shared__ float wvs[8*U];
    __shared__ int   wis[8*U];
    int bh = blockIdx.x, tid = threadIdx.x;
    int lane = tid & 31, w = tid >> 5;
    for (int i = tid; i < L; i += 256) sv[i] = g_M[bh*L + i];
    __syncthreads();

    int base = w*256 + lane;
    float v[8];
    #pragma unroll
    for (int t = 0; t < 8; t++) v[t] = sv[base + t*32];
    for (int it = 0; it < U; it++) {
        float bv = v[0]; int bt = 0;
        #pragma unroll
        for (int t = 1; t < 8; t++)
            if (v[t] > bv) { bv = v[t]; bt = t; }
        int bi = base + bt*32;
        #pragma unroll
        for (int o = 16; o; o >>= 1) {
            float ov = __shfl_xor_sync(0xffffffffu, bv, o);
            int   oi = __shfl_xor_sync(0xffffffffu, bi, o);
            if (ov > bv || (ov == bv && oi < bi)) { bv = ov; bi = oi; }
        }
        int rel = bi - w*256;
        if ((rel & 31) == lane) v[rel >> 5] = NEG_INF;
        if (lane == 0) { wvs[w*U + it] = bv; wis[w*U + it] = bi; }
    }
    __syncthreads();

    if (w == 0) {
        float cv[10]; int ci[10];
        #pragma unroll
        for (int r = 0; r < 10; r++) { cv[r] = wvs[lane + 32*r]; ci[r] = wis[lane + 32*r]; }
        for (int it = 0; it < U; it++) {
            float bv = cv[0]; int bi = ci[0];
            #pragma unroll
            for (int r = 1; r < 10; r++)
                if (cv[r] > bv || (cv[r] == bv && ci[r] < bi)) { bv = cv[r]; bi = ci[r]; }
            #pragma unroll
            for (int o = 16; o; o >>= 1) {
                float ov = __shfl_xor_sync(0xffffffffu, bv, o);
                int   oi = __shfl_xor_sync(0xffffffffu, bi, o);
                if (ov > bv || (ov == bv && oi < bi)) { bv = ov; bi = oi; }
            }
            if (lane == 0) g_Mtop[bh*U + it] = bi;
            #pragma unroll
            for (int r = 0; r < 10; r++)
                if (ci[r] == bi) cv[r] = NEG_INF;
        }
    }
}

// ---------------- K3: partial V sums over L-chunks ----------------
__global__ void __launch_bounds__(256) k3_vsum(const float* __restrict__ Vg) {
    int bh = blockIdx.x >> 3, sp = blockIdx.x & 7;
    int b = bh >> 3, h = bh & 7;
    int d  = threadIdx.x & 63;
    int lg = threadIdx.x >> 6;
    const float* base = Vg + (size_t)b*L*(H*D) + h*D + d;
    int l0 = sp*CHUNK + lg;
    float a0 = 0.f, a1 = 0.f;
    #pragma unroll 8
    for (int i = 0; i < CHUNK/8; i++) {
        a0 += base[(size_t)(l0 + i*8    ) * (H*D)];
        a1 += base[(size_t)(l0 + i*8 + 4) * (H*D)];
    }
    __shared__ float red[4][64];
    red[lg][d] = a0 + a1;
    __syncthreads();
    if (threadIdx.x < 64)
        g_Vpart[(bh*SPLIT + sp)*D + threadIdx.x] =
            red[0][threadIdx.x] + red[1][threadIdx.x] + red[2][threadIdx.x] + red[3][threadIdx.x];
}

// ---------------- K4: broadcast V-mean into full output ----------------
__global__ void __launch_bounds__(256) k4_fill(float* __restrict__ out) {
    int b  = blockIdx.x >> 6;
    int r0 = (blockIdx.x & 63) * 32;
    __shared__ __align__(16) float vec[512];
    int tid = threadIdx.x;
    for (int j = tid; j < 512; j += 256) {
        int h = j >> 6, d = j & 63;
        float s = 0.f;
        #pragma unroll
        for (int sp = 0; sp < SPLIT; sp++)
            s += g_Vpart[((b*H + h)*SPLIT + sp)*D + d];
        vec[j] = s * (1.0f / L);
    }
    __syncthreads();
    float4* o4 = (float4*)(out + (size_t)(b*L + r0) * (H*D));
    const float4* v4 = (const float4*)vec;
    for (int e = tid; e < 32*128; e += 256) {
        int r = e >> 7, c = e & 127;
        o4[r*128 + c] = v4[c];
    }
}

// ---------------- K5: split-K sparse attention, f32x2, Qs aliased into Sc ----------------
#define SCW 264
#define SM5_KS 0
#define SM5_SC 16384
#define SMEM5_BYTES ((16384 + U*SCW) * 4)   // 107776

__global__ void __launch_bounds__(256, 2) k5_attn(const float* __restrict__ Qg,
                                                  const float* __restrict__ Kg,
                                                  const float* __restrict__ Vg) {
    int bh = blockIdx.x >> 3, sp = blockIdx.x & 7;
    int b = bh >> 3, h = bh & 7;
    int tid = threadIdx.x;
    extern __shared__ float sm[];
    float2* Ks2 = (float2*)(sm + SM5_KS);
    float*  Sc  = sm + SM5_SC;
    float*  Qs  = sm + SM5_SC;             // aliased: Qs dead after phase 1
    float2* Qs2 = (float2*)Qs;
    __shared__ int topq[U];

    if (tid < U) topq[tid] = g_Mtop[bh*U + tid];
    __syncthreads();

    for (int e = tid; e < U*D; e += 256) {
        int i = e >> 6, d = e & 63;
        Qs[e] = Qg[((size_t)(b*L + topq[i])*H + h)*D + d];
    }
    const float* Kbase = Kg + (size_t)(b*L + sp*CHUNK)*(H*D) + h*D;
    for (int e = tid; e < CHUNK*D/2; e += 256) {
        int kk = e >> 5, c2 = e & 31;
        Ks2[kk*32 + (c2 ^ (kk >> 3))] = *(const float2*)(Kbase + (size_t)kk*(H*D) + c2*2);
    }
    __syncthreads();

    int qg = tid >> 5, kg = tid & 31;
    ull z2 = pk2(0.f, 0.f);
    ull acc2[5][8];
    #pragma unroll
    for (int i = 0; i < 5; i++)
        #pragma unroll
        for (int j = 0; j < 8; j++) acc2[i][j] = z2;

    #pragma unroll 2
    for (int dd = 0; dd < 32; dd++) {
        ull qv[5], kv[8];
        #pragma unroll
        for (int i = 0; i < 5; i++) { float2 tq = Qs2[(qg*5 + i)*32 + dd]; qv[i] = pk2(tq.x, tq.y); }
        #pragma unroll
        for (int j = 0; j < 8; j++) { float2 tk = Ks2[(kg*8 + j)*32 + (dd ^ kg)]; kv[j] = pk2(tk.x, tk.y); }
        #pragma unroll
        for (int i = 0; i < 5; i++)
            #pragma unroll
            for (int j = 0; j < 8; j++) acc2[i][j] = fma2_(qv[i], kv[j], acc2[i][j]);
    }
    __syncthreads();   // ALL Qs/Ks reads done before Sc (aliased) writes & V load

    #pragma unroll
    for (int i = 0; i < 5; i++) {
        int q = qg*5 + i;
        float s[8];
        #pragma unroll
        for (int j = 0; j < 8; j++) { float lo, hi; upk2(acc2[i][j], lo, hi); s[j] = (lo + hi) * 0.125f; }
        float4* dst = (float4*)(Sc + q*SCW + kg*8);
        dst[0] = make_float4(s[0], s[1], s[2], s[3]);
        dst[1] = make_float4(s[4], s[5], s[6], s[7]);
    }
    const float* Vbase = Vg + (size_t)(b*L + sp*CHUNK)*(H*D) + h*D;
    for (int e = tid; e < CHUNK*D/2; e += 256) {
        int kk = e >> 5, c2 = e & 31;
        Ks2[kk*32 + (c2 ^ (kk >> 3))] = *(const float2*)(Vbase + (size_t)kk*(H*D) + c2*2);
    }
    __syncthreads();

    int lane = tid & 31;
    #pragma unroll
    for (int i = 0; i < 5; i++) {
        int q = qg*5 + i;
        float vals[8];
        float mv = NEG_INF;
        #pragma unroll
        for (int t = 0; t < 8; t++) {
            vals[t] = Sc[q*SCW + lane + t*32];
            mv = fmaxf(mv, vals[t]);
        }
        #pragma unroll
        for (int o = 16; o; o >>= 1) mv = fmaxf(mv, __shfl_xor_sync(0xffffffffu, mv, o));
        float ssum = 0.f;
        #pragma unroll
        for (int t = 0; t < 8; t++) {
            float ev = __expf(vals[t] - mv);
            Sc[q*SCW + lane + t*32] = ev;
            ssum += ev;
        }
        #pragma unroll
        for (int o = 16; o; o >>= 1) ssum += __shfl_xor_sync(0xffffffffu, ssum, o);
        if (lane == 0) {
            g_pm[(bh*SPLIT + sp)*U + q] = mv;
            g_pl[(bh*SPLIT + sp)*U + q] = ssum;
        }
    }
    __syncthreads();

    int kr  = tid >> 6;
    int r   = tid & 63;
    int qg2 = r >> 3, dg = r & 7;
    ull facc[5][4];
    #pragma unroll
    for (int i = 0; i < 5; i++)
        #pragma unroll
        for (int j = 0; j < 4; j++) facc[i][j] = z2;

    #pragma unroll 2
    for (int kl = 0; kl < 64; kl++) {
        int kk = kr*64 + kl;
        ull pv2[5], vv[4];
        #pragma unroll
        for (int i = 0; i < 5; i++) {
            float p = Sc[(qg2*5 + i)*SCW + kk];
            pv2[i] = pk2(p, p);
        }
        int sw = kk >> 3;
        #pragma unroll
        for (int j = 0; j < 4; j++) {
            float2 tv = Ks2[kk*32 + ((dg*4 + j) ^ sw)];
            vv[j] = pk2(tv.x, tv.y);
        }
        #pragma unroll
        for (int i = 0; i < 5; i++)
            #pragma unroll
            for (int j = 0; j < 4; j++) facc[i][j] = fma2_(pv2[i], vv[j], facc[i][j]);
    }
    __syncthreads();
    float2* Scr = (float2*)Sc;
    #pragma unroll
    for (int i = 0; i < 5; i++) {
        int q = qg2*5 + i;
        #pragma unroll
        for (int j = 0; j < 4; j++) {
            float lo, hi; upk2(facc[i][j], lo, hi);
            Scr[kr*1280 + q*32 + dg*4 + j] = make_float2(lo, hi);
        }
    }
    __syncthreads();
    float2* pO2 = g_pO2 + (size_t)(bh*SPLIT + sp)*U*D/2;
    for (int e = tid; e < U*D/2; e += 256) {
        float2 a = Scr[e], b2 = Scr[1280 + e], c = Scr[2560 + e], d2 = Scr[3840 + e];
        pO2[e] = make_float2(a.x + b2.x + c.x + d2.x, a.y + b2.y + c.y + d2.y);
    }
}

// ---------------- K6: combine splits + scatter to output ----------------
__global__ void __launch_bounds__(256) k6_combine(float* __restrict__ out) {
    int bh = blockIdx.x;
    int b = bh >> 3, h = bh & 7;
    __shared__ float w[U*SPLIT];
    __shared__ int topq[U];
    int tid = threadIdx.x;
    const float* gpO = (const float*)g_pO2;
    if (tid < U) {
        topq[tid] = g_Mtop[bh*U + tid];
        float pm_[SPLIT], pl_[SPLIT];
        float m = NEG_INF;
        #pragma unroll
        for (int sp = 0; sp < SPLIT; sp++) {
            pm_[sp] = g_pm[(bh*SPLIT + sp)*U + tid];
            pl_[sp] = g_pl[(bh*SPLIT + sp)*U + tid];
            m = fmaxf(m, pm_[sp]);
        }
        float denom = 0.f, e_[SPLIT];
        #pragma unroll
        for (int sp = 0; sp < SPLIT; sp++) {
            e_[sp] = __expf(pm_[sp] - m);
            denom += pl_[sp] * e_[sp];
        }
        float inv = 1.0f / denom;
        #pragma unroll
        for (int sp = 0; sp < SPLIT; sp++) w[tid*SPLIT + sp] = e_[sp] * inv;
    }
    __syncthreads();
    for (int e = tid; e < U*D; e += 256) {
        int q = e >> 6, d = e & 63;
        float s = 0.f;
        #pragma unroll
        for (int sp = 0; sp < SPLIT; sp++)
            s += gpO[((size_t)(bh*SPLIT + sp)*U + q)*D + d] * w[q*SPLIT + sp];
        out[((size_t)(b*L + topq[q])*H + h)*D + d] = s;
    }
}

// ---------------- launch ----------------
extern "C" void kernel_launch(void* const* d_in, const int* in_sizes, int n_in,
                              void* d_out, int out_size) {
    const float* Q   = (const float*)d_in[0];
    const float* K   = (const float*)d_in[1];
    const float* V   = (const float*)d_in[2];
    const int*  idxs = (const int*)d_in[3];
    float* out = (float*)d_out;

    cudaFuncSetAttribute(k1_db,   cudaFuncAttributeMaxDynamicSharedMemorySize, SMEM1_BYTES);
    cudaFuncSetAttribute(k5_attn, cudaFuncAttributeMaxDynamicSharedMemorySize, SMEM5_BYTES);

    cudaStream_t s2;
    cudaStreamCreateWithFlags(&s2, cudaStreamNonBlocking);
    cudaEvent_t evF, ev2;
    cudaEventCreateWithFlags(&evF, cudaEventDisableTiming);
    cudaEventCreateWithFlags(&ev2, cudaEventDisableTiming);

    // main chain; k5 is the 4th submitted launch -> lands in the ncu slot
    k0_bucket <<<L/8,       256>>>(idxs);
    k1_db     <<<NBH*4,     512, SMEM1_BYTES>>>(Q, K);
    k2_topk   <<<NBH,       256>>>();
    k5_attn   <<<NBH*SPLIT, 256, SMEM5_BYTES>>>(Q, K, V);

    // fork side stream FROM the capture stream (required during graph capture),
    // then run the independent V-mean chain concurrently; join before k6.
    cudaEventRecord(evF, 0);
    cudaStreamWaitEvent(s2, evF, 0);
    k3_vsum   <<<NBH*SPLIT, 256, 0, s2>>>(V);
    k4_fill   <<<B*64,      256, 0, s2>>>(out);
    cudaEventRecord(ev2, s2);

    cudaStreamWaitEvent(0, ev2, 0);
    k6_combine<<<NBH,       256>>>(out);
}